// round 1
// baseline (speedup 1.0000x reference)
#include <cuda_runtime.h>

#define N_NODES 100000
#define D 128
#define N_EDGES 400000
#define BN_EPS 1e-5f

#define GEMM_WARPS 8
#define TM 8            // rows per warp
#define WPAD 132        // padded row (words) for transposed W in smem, keeps 16B align

// Scratch (allocation-free rule: device globals only)
__device__ float g_sum[D];
__device__ float g_sumsq[D];
__device__ float g_scale[D];
__device__ float g_shift[D];
__device__ float g_h[(size_t)N_NODES * D];

// ---------------------------------------------------------------------------
// K0: zero stat accumulators (must run every launch; graph replays)
// ---------------------------------------------------------------------------
__global__ void k_zero() {
    int t = threadIdx.x;
    g_sum[t] = 0.f;
    g_sumsq[t] = 0.f;
}

// ---------------------------------------------------------------------------
// K1: per-column sum / sumsq. One thread per column, blocks stride rows.
// ---------------------------------------------------------------------------
__global__ void k_colsum(const float* __restrict__ x) {
    int c = threadIdx.x;
    float s = 0.f, s2 = 0.f;
#pragma unroll 4
    for (int r = blockIdx.x; r < N_NODES; r += gridDim.x) {
        float v = x[(size_t)r * D + c];
        s += v;
        s2 += v * v;
    }
    atomicAdd(&g_sum[c], s);
    atomicAdd(&g_sumsq[c], s2);
}

// ---------------------------------------------------------------------------
// K2: fold BN into per-column scale/shift
// ---------------------------------------------------------------------------
__global__ void k_stats(const float* __restrict__ gamma, const float* __restrict__ beta) {
    int c = threadIdx.x;
    const float inv_n = 1.f / (float)N_NODES;
    float mu = g_sum[c] * inv_n;
    float var = g_sumsq[c] * inv_n - mu * mu;
    float rs = rsqrtf(var + BN_EPS);
    float sc = gamma[c] * rs;
    g_scale[c] = sc;
    g_shift[c] = beta[c] - mu * sc;
}

// ---------------------------------------------------------------------------
// K3: fused BN -> ReLU -> GEMM (h = y @ W^T), writes g_h and out = h*h.
// Block = 8 warps; each warp computes TM=8 rows, each lane 4 consecutive cols.
// W kept transposed in smem (Wsh[k][j]); packed f32x2 FMA for 2x fp32 rate.
// ---------------------------------------------------------------------------
extern __shared__ float sm_gemm[];

__global__ void __launch_bounds__(256, 2) k_gemm(const float* __restrict__ x,
                                                 const float* __restrict__ W,
                                                 float* __restrict__ out) {
    float* Wsh = sm_gemm;                       // D * WPAD
    float* ysh = Wsh + D * WPAD;                // GEMM_WARPS * TM * D
    float* ssc = ysh + GEMM_WARPS * TM * D;     // D
    float* ssh = ssc + D;                       // D

    int tid = threadIdx.x;

    // Load W transposed: Wsh[k*WPAD + j] = W[j*D + k]
    for (int i = tid; i < D * D; i += blockDim.x) {
        int j = i / D;
        int k = i - j * D;
        Wsh[k * WPAD + j] = W[i];
    }
    if (tid < D) {
        ssc[tid] = g_scale[tid];
        ssh[tid] = g_shift[tid];
    }
    __syncthreads();

    int warp = tid >> 5;
    int lane = tid & 31;
    float* myY = ysh + warp * TM * D;

    float sc[4], sh[4];
#pragma unroll
    for (int i = 0; i < 4; i++) {
        sc[i] = ssc[4 * lane + i];
        sh[i] = ssh[4 * lane + i];
    }

    const int ntiles = (N_NODES + GEMM_WARPS * TM - 1) / (GEMM_WARPS * TM);
    for (int tile = blockIdx.x; tile < ntiles; tile += gridDim.x) {
        int row0 = tile * (GEMM_WARPS * TM) + warp * TM;

        __syncwarp();   // prior k-loop reads of ysh done before restage
#pragma unroll
        for (int r = 0; r < TM; r++) {
            int row = row0 + r;
            if (row < N_NODES) {
                float4 v = *(const float4*)&x[(size_t)row * D + 4 * lane];
                v.x = fmaxf(0.f, fmaf(v.x, sc[0], sh[0]));
                v.y = fmaxf(0.f, fmaf(v.y, sc[1], sh[1]));
                v.z = fmaxf(0.f, fmaf(v.z, sc[2], sh[2]));
                v.w = fmaxf(0.f, fmaf(v.w, sc[3], sh[3]));
                *(float4*)&myY[r * D + 4 * lane] = v;
            }
        }
        __syncwarp();

        unsigned long long acc[TM][2];
#pragma unroll
        for (int r = 0; r < TM; r++) { acc[r][0] = 0ULL; acc[r][1] = 0ULL; }

#pragma unroll 8
        for (int k = 0; k < D; k++) {
            float4 w4 = *(const float4*)&Wsh[k * WPAD + 4 * lane];
            unsigned long long w01, w23;
            asm("mov.b64 %0, {%1,%2};" : "=l"(w01) : "f"(w4.x), "f"(w4.y));
            asm("mov.b64 %0, {%1,%2};" : "=l"(w23) : "f"(w4.z), "f"(w4.w));
#pragma unroll
            for (int r = 0; r < TM; r++) {
                float yv = myY[r * D + k];
                unsigned long long yy;
                asm("mov.b64 %0, {%1,%1};" : "=l"(yy) : "f"(yv));
                asm("fma.rn.f32x2 %0, %1, %2, %0;" : "+l"(acc[r][0]) : "l"(yy), "l"(w01));
                asm("fma.rn.f32x2 %0, %1, %2, %0;" : "+l"(acc[r][1]) : "l"(yy), "l"(w23));
            }
        }

#pragma unroll
        for (int r = 0; r < TM; r++) {
            int row = row0 + r;
            if (row < N_NODES) {
                float4 hv;
                asm("mov.b64 {%0,%1}, %2;" : "=f"(hv.x), "=f"(hv.y) : "l"(acc[r][0]));
                asm("mov.b64 {%0,%1}, %2;" : "=f"(hv.z), "=f"(hv.w) : "l"(acc[r][1]));
                *(float4*)&g_h[(size_t)row * D + 4 * lane] = hv;
                float4 o = make_float4(hv.x * hv.x, hv.y * hv.y, hv.z * hv.z, hv.w * hv.w);
                *(float4*)&out[(size_t)row * D + 4 * lane] = o;
            }
        }
    }
}

// ---------------------------------------------------------------------------
// K4: edge aggregation. One warp per edge; lane handles 4 consecutive floats.
// out[row] += w * h[col]   via red.global.add.v4.f32 (sm_90+ vector reduction)
// ---------------------------------------------------------------------------
__global__ void k_edges(const int* __restrict__ eidx, const float* __restrict__ ew,
                        float* __restrict__ out) {
    int wg = (int)((blockIdx.x * (unsigned)blockDim.x + threadIdx.x) >> 5);
    int lane = threadIdx.x & 31;
    if (wg >= N_EDGES) return;
    int r = eidx[wg];
    int c = eidx[N_EDGES + wg];
    float w = ew[wg];
    float4 m = *(const float4*)&g_h[(size_t)c * D + 4 * lane];
    m.x *= w; m.y *= w; m.z *= w; m.w *= w;
    float* dst = &out[(size_t)r * D + 4 * lane];
    asm volatile("red.global.add.v4.f32 [%0], {%1,%2,%3,%4};"
                 :: "l"(dst), "f"(m.x), "f"(m.y), "f"(m.z), "f"(m.w)
                 : "memory");
}

// ---------------------------------------------------------------------------
extern "C" void kernel_launch(void* const* d_in, const int* in_sizes, int n_in,
                              void* d_out, int out_size) {
    const float* x     = (const float*)d_in[0];
    const int*   eidx  = (const int*)d_in[1];
    const float* ew    = (const float*)d_in[2];
    const float* gamma = (const float*)d_in[3];
    const float* beta  = (const float*)d_in[4];
    const float* W     = (const float*)d_in[5];
    float* out = (float*)d_out;

    k_zero<<<1, D>>>();
    k_colsum<<<464, D>>>(x);
    k_stats<<<1, D>>>(gamma, beta);

    const size_t smem = (size_t)(D * WPAD + GEMM_WARPS * TM * D + 2 * D) * sizeof(float);
    cudaFuncSetAttribute(k_gemm, cudaFuncAttributeMaxDynamicSharedMemorySize, (int)smem);
    k_gemm<<<304, 256, smem>>>(x, W, out);

    int eblocks = (N_EDGES * 32 + 255) / 256;   // one warp per edge
    k_edges<<<eblocks, 256>>>(eidx, ew, out);
}